// round 8
// baseline (speedup 1.0000x reference)
#include <cuda_runtime.h>
#include <cuda_bf16.h>

// Problem constants (fixed shapes per reference setup_inputs)
#define B_   32
#define C_   4
#define P_   (360 * 640)      // 230400
#define L_   5
#define NVEC (P_ / 4)         // 57600 vec4 groups per batch

#define NBLK 60               // blocks per batch (grid 1920 — best measured)
#define TPB  256

#define DELTA_V 1.0f
#define DELTA_D 6.0f

typedef unsigned long long ull;

// ---- static scratch (no allocation allowed) ----
__device__ float    g_sumsf[B_ * L_ * C_];       // global channel sums
__device__ int      g_cnt  [B_ * L_];            // global counts
__device__ float    g_means[B_ * (L_ + 1) * C_]; // lane 0 = zeros
__device__ int      g_valid[B_ * (L_ + 1)];      // lane 0 = 0
__device__ float    g_scalars[4];                // 0 dist_sum, 1 point_count, 2 var_loss
__device__ int      g_acc_done;
__device__ int      g_dist_done;
__device__ unsigned g_tpack[B_ * NVEC];          // 4 uint8 labels per word

__device__ __forceinline__ ull pack2(float a, float b) {
    ull r;
    asm("mov.b64 %0, {%1, %2};" : "=l"(r) : "f"(a), "f"(b));
    return r;
}
__device__ __forceinline__ void unpack2(ull v, float& a, float& b) {
    asm("mov.b64 {%0, %1}, %2;" : "=f"(a), "=f"(b) : "l"(v));
}
__device__ __forceinline__ float sqrt_approx(float x) {
    float r;
    asm("sqrt.approx.f32 %0, %1;" : "=f"(r) : "f"(x));
    return r;
}

// --------------------------------------------------------------------------
// Pass 1: per-(batch, lane) counts and channel sums. Packed f32x2 predicated
// accumulation (non-volatile asm, unroll 1, occupancy-capped regs), plus
// uint8 label re-pack for pass 2. Last-finishing block computes means,
// validity, point_count, and the push loss.
__global__ void __launch_bounds__(TPB, 5) accum_kernel(const int* __restrict__ tg,
                                                       const float* __restrict__ emb) {
    const int b = blockIdx.y;
    const int4*   t4 = (const int4*)(tg + (size_t)b * P_);
    const float4* e4 = (const float4*)(emb + (size_t)b * C_ * P_);
    unsigned*     tp = g_tpack + (size_t)b * NVEC;

    ull acc01[L_], acc23[L_];   // packed {ch0,ch1} and {ch2,ch3} per lane
    int cnt[L_];
#pragma unroll
    for (int l = 0; l < L_; l++) { acc01[l] = 0ULL; acc23[l] = 0ULL; cnt[l] = 0; }

    // One point: 2 packs, then per lane 1 setp + 2 predicated add.f32x2 +
    // 1 predicated add.s32. Non-volatile: ptxas may schedule freely.
#define DO_POINT(TT, F0, F1, F2, F3)                                           \
    {                                                                          \
        const int _t   = (TT);                                                 \
        const ull _p01 = pack2((F0), (F1));                                    \
        const ull _p23 = pack2((F2), (F3));                                    \
        _Pragma("unroll")                                                      \
        for (int _l = 0; _l < L_; _l++) {                                      \
            asm("{\n\t"                                                        \
                ".reg .pred p;\n\t"                                            \
                "setp.eq.s32 p, %3, %4;\n\t"                                   \
                "@p add.rn.f32x2 %0, %0, %5;\n\t"                              \
                "@p add.rn.f32x2 %1, %1, %6;\n\t"                              \
                "@p add.s32 %2, %2, 1;\n\t"                                    \
                "}"                                                            \
                : "+l"(acc01[_l]), "+l"(acc23[_l]), "+r"(cnt[_l])              \
                : "r"(_t), "r"(_l + 1), "l"(_p01), "l"(_p23));                 \
        }                                                                      \
    }

#pragma unroll 1
    for (int i = blockIdx.x * blockDim.x + threadIdx.x; i < NVEC;
         i += gridDim.x * blockDim.x) {
        int4   tv  = t4[i];
        float4 ev0 = e4[i];
        float4 ev1 = e4[(size_t)NVEC + i];
        float4 ev2 = e4[(size_t)2 * NVEC + i];
        float4 ev3 = e4[(size_t)3 * NVEC + i];

        tp[i] = (unsigned)tv.x | ((unsigned)tv.y << 8) |
                ((unsigned)tv.z << 16) | ((unsigned)tv.w << 24);

        DO_POINT(tv.x, ev0.x, ev1.x, ev2.x, ev3.x);
        DO_POINT(tv.y, ev0.y, ev1.y, ev2.y, ev3.y);
        DO_POINT(tv.z, ev0.z, ev1.z, ev2.z, ev3.z);
        DO_POINT(tv.w, ev0.w, ev1.w, ev2.w, ev3.w);
    }
#undef DO_POINT

    // unpack + warp reduce (R1 epilogue)
    float s[L_][C_];
#pragma unroll
    for (int l = 0; l < L_; l++) {
        unpack2(acc01[l], s[l][0], s[l][1]);
        unpack2(acc23[l], s[l][2], s[l][3]);
    }
#pragma unroll
    for (int l = 0; l < L_; l++) {
#pragma unroll
        for (int off = 16; off > 0; off >>= 1) {
            cnt[l] += __shfl_down_sync(0xffffffffu, cnt[l], off);
#pragma unroll
            for (int c = 0; c < C_; c++)
                s[l][c] += __shfl_down_sync(0xffffffffu, s[l][c], off);
        }
    }

    __shared__ float ss[L_ * C_];
    __shared__ int   sc[L_];
    if (threadIdx.x < L_ * C_) ss[threadIdx.x] = 0.0f;
    if (threadIdx.x < L_)      sc[threadIdx.x] = 0;
    __syncthreads();

    if ((threadIdx.x & 31) == 0) {
#pragma unroll
        for (int l = 0; l < L_; l++) {
            atomicAdd(&sc[l], cnt[l]);
#pragma unroll
            for (int c = 0; c < C_; c++) atomicAdd(&ss[l * C_ + c], s[l][c]);
        }
    }
    __syncthreads();

    if (threadIdx.x < L_ * C_)
        atomicAdd(&g_sumsf[b * L_ * C_ + threadIdx.x], ss[threadIdx.x]);
    if (threadIdx.x < L_)
        atomicAdd(&g_cnt[b * L_ + threadIdx.x], sc[threadIdx.x]);

    // ---- last-finishing block: means + validity + push loss ----
    __shared__ int s_last;
    __syncthreads();
    if (threadIdx.x == 0) {
        __threadfence();
        s_last = (atomicAdd(&g_acc_done, 1) == NBLK * B_ - 1) ? 1 : 0;
    }
    __syncthreads();
    if (!s_last) return;

    if (threadIdx.x < 32) {
        const int bb = threadIdx.x;  // batch

        float mean[L_][C_];
        int   vld[L_];
        float pc_local = 0.0f;
#pragma unroll
        for (int l = 0; l < L_; l++) {
            const int cc = g_cnt[bb * L_ + l];
            vld[l] = (cc > 1);
            const float inv = 1.0f / (float)max(cc, 1);
#pragma unroll
            for (int ch = 0; ch < C_; ch++) {
                const float m = g_sumsf[(bb * L_ + l) * C_ + ch] * inv;
                mean[l][ch] = m;
                g_means[(bb * (L_ + 1) + (l + 1)) * C_ + ch] = m;
                g_sumsf[(bb * L_ + l) * C_ + ch] = 0.0f;   // reset for replay
            }
            g_valid[bb * (L_ + 1) + (l + 1)] = vld[l];
            g_cnt[bb * L_ + l] = 0;                        // reset for replay
            if (vld[l]) pc_local += (float)cc;
        }
#pragma unroll
        for (int ch = 0; ch < C_; ch++) g_means[bb * (L_ + 1) * C_ + ch] = 0.0f;
        g_valid[bb * (L_ + 1)] = 0;

        float psum = 0.0f;
        int npairs = 0;
#pragma unroll
        for (int i = 0; i < L_; i++) {
#pragma unroll
            for (int j = i + 1; j < L_; j++) {
                if (vld[i] && vld[j]) {
                    float sq = 0.0f;
#pragma unroll
                    for (int ch = 0; ch < C_; ch++) {
                        const float d = mean[i][ch] - mean[j][ch];
                        sq = fmaf(d, d, sq);
                    }
                    const float pd = sqrtf(fmaxf(sq, 1e-12f));
                    const float ph = fmaxf(DELTA_D - pd, 0.0f);
                    psum += ph * ph;
                    npairs++;
                }
            }
        }
        const float var_b = (npairs > 0) ? psum / (float)npairs : 0.0f;
        const float has   = (npairs > 0) ? 1.0f : 0.0f;

        float var_sum = var_b, nb = has, pc = pc_local;
#pragma unroll
        for (int off = 16; off > 0; off >>= 1) {
            var_sum += __shfl_down_sync(0xffffffffu, var_sum, off);
            nb      += __shfl_down_sync(0xffffffffu, nb, off);
            pc      += __shfl_down_sync(0xffffffffu, pc, off);
        }
        if (threadIdx.x == 0) {
            g_scalars[0] = 0.0f;   // dist accumulator
            g_scalars[1] = pc;     // point_count
            g_scalars[2] = (nb > 0.0f) ? var_sum / fmaxf(nb, 1.0f) : 0.0f;
            g_acc_done = 0;        // reset for next graph replay
            __threadfence();
        }
    }
}

// --------------------------------------------------------------------------
// Pass 2: per-point pull hinge^2 reading packed uint8 labels (4 B/group
// instead of 16 B); last block writes the final scalar. (R7 verbatim.)
__global__ void dist_kernel(const float* __restrict__ emb,
                            float* __restrict__ out) {
    const int b = blockIdx.y;
    __shared__ float sm[(L_ + 1) * C_];
    __shared__ int   sv[L_ + 1];
    if (threadIdx.x < (L_ + 1) * C_) sm[threadIdx.x] = g_means[b * (L_ + 1) * C_ + threadIdx.x];
    if (threadIdx.x < (L_ + 1))      sv[threadIdx.x] = g_valid[b * (L_ + 1) + threadIdx.x];
    __syncthreads();

    const unsigned* tp = g_tpack + (size_t)b * NVEC;
    const float4*   e4 = (const float4*)(emb + (size_t)b * C_ * P_);

    float local = 0.0f;
    for (int i = blockIdx.x * blockDim.x + threadIdx.x; i < NVEC;
         i += gridDim.x * blockDim.x) {
        const unsigned u = tp[i];
        float4 ev[C_];
#pragma unroll
        for (int c = 0; c < C_; c++) ev[c] = e4[(size_t)c * NVEC + i];

        int tj[4] = {(int)(u & 255u), (int)((u >> 8) & 255u),
                     (int)((u >> 16) & 255u), (int)(u >> 24)};
#pragma unroll
        for (int j = 0; j < 4; j++) {
            const int tt = tj[j];
            if (sv[tt]) {
                float sq = 0.0f;
#pragma unroll
                for (int c = 0; c < C_; c++) {
                    const float d = ((const float*)&ev[c])[j] - sm[tt * C_ + c];
                    sq = fmaf(d, d, sq);
                }
                const float dist = sqrt_approx(fmaxf(sq, 1e-12f));
                const float h = dist - DELTA_V;
                if (h > 0.0f) local = fmaf(h, h, local);
            }
        }
    }

#pragma unroll
    for (int off = 16; off > 0; off >>= 1)
        local += __shfl_down_sync(0xffffffffu, local, off);

    __shared__ float sred;
    if (threadIdx.x == 0) sred = 0.0f;
    __syncthreads();
    if ((threadIdx.x & 31) == 0) atomicAdd(&sred, local);
    __syncthreads();

    if (threadIdx.x == 0) {
        atomicAdd(&g_scalars[0], sred);
        __threadfence();
        const int old = atomicAdd(&g_dist_done, 1);
        if (old == NBLK * B_ - 1) {
            const float ds = g_scalars[0];
            const float pc = g_scalars[1];
            const float dl = (pc > 0.0f) ? ds / fmaxf(pc, 1.0f) : 0.0f;
            out[0] = dl + g_scalars[2];
            g_dist_done = 0;       // reset for next graph replay
            __threadfence();
        }
    }
}

// --------------------------------------------------------------------------
extern "C" void kernel_launch(void* const* d_in, const int* in_sizes, int n_in,
                              void* d_out, int out_size) {
    const int*   tg  = (const int*)d_in[0];    // targets [32,360,640] int32
    const float* emb = (const float*)d_in[1];  // embedding [32,4,360,640] f32
    float* out = (float*)d_out;

    dim3 grid(NBLK, B_);
    accum_kernel<<<grid, TPB>>>(tg, emb);
    dist_kernel<<<grid, TPB>>>(emb, out);
}

// round 9
// speedup vs baseline: 1.0304x; 1.0304x over previous
#include <cuda_runtime.h>
#include <cuda_bf16.h>

// Problem constants (fixed shapes per reference setup_inputs)
#define B_   32
#define C_   4
#define P_   (360 * 640)      // 230400
#define L_   5
#define NVEC (P_ / 4)         // 57600 vec4 groups per batch

#define NBLK 75               // 75*256*3 == NVEC exactly (even division)
#define TPB  256

#define DELTA_V 1.0f
#define DELTA_D 6.0f

// ---- static scratch (no allocation allowed) ----
__device__ float    g_sumsf[B_ * L_ * C_];       // global channel sums
__device__ int      g_cnt  [B_ * L_];            // global counts
__device__ float    g_means[B_ * (L_ + 1) * C_]; // lane 0 = zeros
__device__ int      g_valid[B_ * (L_ + 1)];      // lane 0 = 0
__device__ float    g_scalars[4];                // 0 dist_sum, 1 point_count, 2 var_loss
__device__ int      g_acc_done;
__device__ int      g_dist_done;
__device__ unsigned g_tpack[B_ * NVEC];          // 4 uint8 labels per word

__device__ __forceinline__ float sqrt_approx(float x) {
    float r;
    asm("sqrt.approx.f32 %0, %1;" : "=f"(r) : "f"(x));
    return r;
}

// --------------------------------------------------------------------------
// Pass 1: per-(batch, lane) counts and channel sums. Scalar predicated FADD
// accumulation (1 setp + 4 pred-FADD + 1 pred-IADD per lane per point),
// non-volatile asm. Plus uint8 label re-pack for pass 2. Last-finishing
// block computes means/validity/point_count and the push loss.
__global__ void accum_kernel(const int* __restrict__ tg,
                             const float* __restrict__ emb) {
    const int b = blockIdx.y;
    const int4*   t4 = (const int4*)(tg + (size_t)b * P_);
    const float4* e4 = (const float4*)(emb + (size_t)b * C_ * P_);
    unsigned*     tp = g_tpack + (size_t)b * NVEC;

    float s[L_][C_];
    int cnt[L_];
#pragma unroll
    for (int l = 0; l < L_; l++) {
        cnt[l] = 0;
#pragma unroll
        for (int c = 0; c < C_; c++) s[l][c] = 0.0f;
    }

#define DO_POINT(TT, F0, F1, F2, F3)                                           \
    {                                                                          \
        const int _t = (TT);                                                   \
        _Pragma("unroll")                                                      \
        for (int _l = 0; _l < L_; _l++) {                                      \
            asm("{\n\t"                                                        \
                ".reg .pred p;\n\t"                                            \
                "setp.eq.s32 p, %5, %6;\n\t"                                   \
                "@p add.f32 %0, %0, %7;\n\t"                                   \
                "@p add.f32 %1, %1, %8;\n\t"                                   \
                "@p add.f32 %2, %2, %9;\n\t"                                   \
                "@p add.f32 %3, %3, %10;\n\t"                                  \
                "@p add.s32 %4, %4, 1;\n\t"                                    \
                "}"                                                            \
                : "+f"(s[_l][0]), "+f"(s[_l][1]), "+f"(s[_l][2]),              \
                  "+f"(s[_l][3]), "+r"(cnt[_l])                                \
                : "r"(_t), "r"(_l + 1), "f"(F0), "f"(F1), "f"(F2), "f"(F3));   \
        }                                                                      \
    }

#pragma unroll 1
    for (int i = blockIdx.x * blockDim.x + threadIdx.x; i < NVEC;
         i += gridDim.x * blockDim.x) {
        int4   tv  = t4[i];
        float4 ev0 = e4[i];
        float4 ev1 = e4[(size_t)NVEC + i];
        float4 ev2 = e4[(size_t)2 * NVEC + i];
        float4 ev3 = e4[(size_t)3 * NVEC + i];

        tp[i] = (unsigned)tv.x | ((unsigned)tv.y << 8) |
                ((unsigned)tv.z << 16) | ((unsigned)tv.w << 24);

        DO_POINT(tv.x, ev0.x, ev1.x, ev2.x, ev3.x);
        DO_POINT(tv.y, ev0.y, ev1.y, ev2.y, ev3.y);
        DO_POINT(tv.z, ev0.z, ev1.z, ev2.z, ev3.z);
        DO_POINT(tv.w, ev0.w, ev1.w, ev2.w, ev3.w);
    }
#undef DO_POINT

    // warp reduce
#pragma unroll
    for (int l = 0; l < L_; l++) {
#pragma unroll
        for (int off = 16; off > 0; off >>= 1) {
            cnt[l] += __shfl_down_sync(0xffffffffu, cnt[l], off);
#pragma unroll
            for (int c = 0; c < C_; c++)
                s[l][c] += __shfl_down_sync(0xffffffffu, s[l][c], off);
        }
    }

    __shared__ float ss[L_ * C_];
    __shared__ int   sc[L_];
    if (threadIdx.x < L_ * C_) ss[threadIdx.x] = 0.0f;
    if (threadIdx.x < L_)      sc[threadIdx.x] = 0;
    __syncthreads();

    if ((threadIdx.x & 31) == 0) {
#pragma unroll
        for (int l = 0; l < L_; l++) {
            atomicAdd(&sc[l], cnt[l]);
#pragma unroll
            for (int c = 0; c < C_; c++) atomicAdd(&ss[l * C_ + c], s[l][c]);
        }
    }
    __syncthreads();

    if (threadIdx.x < L_ * C_)
        atomicAdd(&g_sumsf[b * L_ * C_ + threadIdx.x], ss[threadIdx.x]);
    if (threadIdx.x < L_)
        atomicAdd(&g_cnt[b * L_ + threadIdx.x], sc[threadIdx.x]);

    // ---- last-finishing block: means + validity + push loss ----
    __shared__ int s_last;
    __syncthreads();
    if (threadIdx.x == 0) {
        __threadfence();
        s_last = (atomicAdd(&g_acc_done, 1) == NBLK * B_ - 1) ? 1 : 0;
    }
    __syncthreads();
    if (!s_last) return;

    if (threadIdx.x < 32) {
        const int bb = threadIdx.x;  // batch

        float mean[L_][C_];
        int   vld[L_];
        float pc_local = 0.0f;
#pragma unroll
        for (int l = 0; l < L_; l++) {
            const int cc = g_cnt[bb * L_ + l];
            vld[l] = (cc > 1);
            const float inv = 1.0f / (float)max(cc, 1);
#pragma unroll
            for (int ch = 0; ch < C_; ch++) {
                const float m = g_sumsf[(bb * L_ + l) * C_ + ch] * inv;
                mean[l][ch] = m;
                g_means[(bb * (L_ + 1) + (l + 1)) * C_ + ch] = m;
                g_sumsf[(bb * L_ + l) * C_ + ch] = 0.0f;   // reset for replay
            }
            g_valid[bb * (L_ + 1) + (l + 1)] = vld[l];
            g_cnt[bb * L_ + l] = 0;                        // reset for replay
            if (vld[l]) pc_local += (float)cc;
        }
#pragma unroll
        for (int ch = 0; ch < C_; ch++) g_means[bb * (L_ + 1) * C_ + ch] = 0.0f;
        g_valid[bb * (L_ + 1)] = 0;

        float psum = 0.0f;
        int npairs = 0;
#pragma unroll
        for (int i = 0; i < L_; i++) {
#pragma unroll
            for (int j = i + 1; j < L_; j++) {
                if (vld[i] && vld[j]) {
                    float sq = 0.0f;
#pragma unroll
                    for (int ch = 0; ch < C_; ch++) {
                        const float d = mean[i][ch] - mean[j][ch];
                        sq = fmaf(d, d, sq);
                    }
                    const float pd = sqrtf(fmaxf(sq, 1e-12f));
                    const float ph = fmaxf(DELTA_D - pd, 0.0f);
                    psum += ph * ph;
                    npairs++;
                }
            }
        }
        const float var_b = (npairs > 0) ? psum / (float)npairs : 0.0f;
        const float has   = (npairs > 0) ? 1.0f : 0.0f;

        float var_sum = var_b, nb = has, pc = pc_local;
#pragma unroll
        for (int off = 16; off > 0; off >>= 1) {
            var_sum += __shfl_down_sync(0xffffffffu, var_sum, off);
            nb      += __shfl_down_sync(0xffffffffu, nb, off);
            pc      += __shfl_down_sync(0xffffffffu, pc, off);
        }
        if (threadIdx.x == 0) {
            g_scalars[0] = 0.0f;   // dist accumulator
            g_scalars[1] = pc;     // point_count
            g_scalars[2] = (nb > 0.0f) ? var_sum / fmaxf(nb, 1.0f) : 0.0f;
            g_acc_done = 0;        // reset for next graph replay
            __threadfence();
        }
    }
}

// --------------------------------------------------------------------------
// Pass 2: per-point pull hinge^2 reading packed uint8 labels; last block
// writes the final scalar. (R7 verbatim except NBLK.)
__global__ void dist_kernel(const float* __restrict__ emb,
                            float* __restrict__ out) {
    const int b = blockIdx.y;
    __shared__ float sm[(L_ + 1) * C_];
    __shared__ int   sv[L_ + 1];
    if (threadIdx.x < (L_ + 1) * C_) sm[threadIdx.x] = g_means[b * (L_ + 1) * C_ + threadIdx.x];
    if (threadIdx.x < (L_ + 1))      sv[threadIdx.x] = g_valid[b * (L_ + 1) + threadIdx.x];
    __syncthreads();

    const unsigned* tp = g_tpack + (size_t)b * NVEC;
    const float4*   e4 = (const float4*)(emb + (size_t)b * C_ * P_);

    float local = 0.0f;
    for (int i = blockIdx.x * blockDim.x + threadIdx.x; i < NVEC;
         i += gridDim.x * blockDim.x) {
        const unsigned u = tp[i];
        float4 ev[C_];
#pragma unroll
        for (int c = 0; c < C_; c++) ev[c] = e4[(size_t)c * NVEC + i];

        int tj[4] = {(int)(u & 255u), (int)((u >> 8) & 255u),
                     (int)((u >> 16) & 255u), (int)(u >> 24)};
#pragma unroll
        for (int j = 0; j < 4; j++) {
            const int tt = tj[j];
            if (sv[tt]) {
                float sq = 0.0f;
#pragma unroll
                for (int c = 0; c < C_; c++) {
                    const float d = ((const float*)&ev[c])[j] - sm[tt * C_ + c];
                    sq = fmaf(d, d, sq);
                }
                const float dist = sqrt_approx(fmaxf(sq, 1e-12f));
                const float h = dist - DELTA_V;
                if (h > 0.0f) local = fmaf(h, h, local);
            }
        }
    }

#pragma unroll
    for (int off = 16; off > 0; off >>= 1)
        local += __shfl_down_sync(0xffffffffu, local, off);

    __shared__ float sred;
    if (threadIdx.x == 0) sred = 0.0f;
    __syncthreads();
    if ((threadIdx.x & 31) == 0) atomicAdd(&sred, local);
    __syncthreads();

    if (threadIdx.x == 0) {
        atomicAdd(&g_scalars[0], sred);
        __threadfence();
        const int old = atomicAdd(&g_dist_done, 1);
        if (old == NBLK * B_ - 1) {
            const float ds = g_scalars[0];
            const float pc = g_scalars[1];
            const float dl = (pc > 0.0f) ? ds / fmaxf(pc, 1.0f) : 0.0f;
            out[0] = dl + g_scalars[2];
            g_dist_done = 0;       // reset for next graph replay
            __threadfence();
        }
    }
}

// --------------------------------------------------------------------------
extern "C" void kernel_launch(void* const* d_in, const int* in_sizes, int n_in,
                              void* d_out, int out_size) {
    const int*   tg  = (const int*)d_in[0];    // targets [32,360,640] int32
    const float* emb = (const float*)d_in[1];  // embedding [32,4,360,640] f32
    float* out = (float*)d_out;

    dim3 grid(NBLK, B_);
    accum_kernel<<<grid, TPB>>>(tg, emb);
    dist_kernel<<<grid, TPB>>>(emb, out);
}

// round 10
// speedup vs baseline: 1.1946x; 1.1594x over previous
#include <cuda_runtime.h>
#include <cuda_bf16.h>

// Problem constants (fixed shapes per reference setup_inputs)
#define B_   32
#define C_   4
#define P_   (360 * 640)      // 230400
#define L_   5
#define NVEC (P_ / 4)         // 57600 vec4 groups per batch

#define NBLK 60               // blocks per batch (R1 champion config)
#define TPB  256

#define DELTA_V 1.0f
#define DELTA_D 6.0f

// ---- static scratch (no device allocation allowed) ----
__device__ float    g_sums[B_ * L_ * C_];        // [B][L][C]
__device__ int      g_counts[B_ * L_];           // [B][L]
__device__ float    g_means[B_ * (L_ + 1) * C_]; // [B][6][4], lane 0 = zeros
__device__ int      g_valid[B_ * (L_ + 1)];      // [B][6], lane 0 = 0
__device__ float    g_scalars[4];                // 0: dist_sum, 1: point_count, 2: var_loss
__device__ unsigned g_tpack[B_ * NVEC];          // 4 uint8 labels per word

__device__ __forceinline__ float sqrt_approx(float x) {
    float r;
    asm("sqrt.approx.f32 %0, %1;" : "=f"(r) : "f"(x));
    return r;
}

// --------------------------------------------------------------------------
__global__ void zero_kernel() {
    int i = blockIdx.x * blockDim.x + threadIdx.x;
    if (i < B_ * L_ * C_) g_sums[i] = 0.0f;
    if (i < B_ * L_)      g_counts[i] = 0;
    if (i < 4)            g_scalars[i] = 0.0f;
}

// --------------------------------------------------------------------------
// Pass 1: per-(batch, lane) segment counts and channel sums (R1 mainloop:
// branch-free select + FFMA, plain C so ptxas owns scheduling), plus uint8
// label re-pack for pass 2. Streaming loads (no reuse).
__global__ void accum_kernel(const int* __restrict__ tg,
                             const float* __restrict__ emb) {
    const int b = blockIdx.y;
    const int4*   t4 = (const int4*)(tg + (size_t)b * P_);
    const float4* e4 = (const float4*)(emb + (size_t)b * C_ * P_);
    unsigned*     tp = g_tpack + (size_t)b * NVEC;

    float s[L_][C_];
    int cnt[L_];
#pragma unroll
    for (int l = 0; l < L_; l++) {
        cnt[l] = 0;
#pragma unroll
        for (int c = 0; c < C_; c++) s[l][c] = 0.0f;
    }

    for (int i = blockIdx.x * blockDim.x + threadIdx.x; i < NVEC;
         i += gridDim.x * blockDim.x) {
        int4 tv = __ldcs(&t4[i]);
        float4 ev[C_];
#pragma unroll
        for (int c = 0; c < C_; c++) ev[c] = __ldcs(&e4[(size_t)c * NVEC + i]);

        tp[i] = (unsigned)tv.x | ((unsigned)tv.y << 8) |
                ((unsigned)tv.z << 16) | ((unsigned)tv.w << 24);

        int tj[4] = {tv.x, tv.y, tv.z, tv.w};
#pragma unroll
        for (int j = 0; j < 4; j++) {
            const int tt = tj[j];
#pragma unroll
            for (int l = 0; l < L_; l++) {
                const bool m = (tt == l + 1);
                cnt[l] += m ? 1 : 0;
                const float fm = m ? 1.0f : 0.0f;
#pragma unroll
                for (int c = 0; c < C_; c++)
                    s[l][c] = fmaf(fm, ((const float*)&ev[c])[j], s[l][c]);
            }
        }
    }

    // warp reduce
#pragma unroll
    for (int l = 0; l < L_; l++) {
#pragma unroll
        for (int off = 16; off > 0; off >>= 1) {
            cnt[l] += __shfl_down_sync(0xffffffffu, cnt[l], off);
#pragma unroll
            for (int c = 0; c < C_; c++)
                s[l][c] += __shfl_down_sync(0xffffffffu, s[l][c], off);
        }
    }

    __shared__ float ss[L_ * C_];
    __shared__ int   sc[L_];
    if (threadIdx.x < L_ * C_) ss[threadIdx.x] = 0.0f;
    if (threadIdx.x < L_)      sc[threadIdx.x] = 0;
    __syncthreads();

    if ((threadIdx.x & 31) == 0) {
#pragma unroll
        for (int l = 0; l < L_; l++) {
            atomicAdd(&sc[l], cnt[l]);
#pragma unroll
            for (int c = 0; c < C_; c++) atomicAdd(&ss[l * C_ + c], s[l][c]);
        }
    }
    __syncthreads();

    if (threadIdx.x < L_ * C_)
        atomicAdd(&g_sums[b * L_ * C_ + threadIdx.x], ss[threadIdx.x]);
    if (threadIdx.x < L_)
        atomicAdd(&g_counts[b * L_ + threadIdx.x], sc[threadIdx.x]);
}

// --------------------------------------------------------------------------
// Means, validity, point_count, and the full push (distance) loss.
// 1 warp, thread b handles batch b. (R1 verbatim.)
__global__ void means_kernel() {
    const int b = threadIdx.x;  // 0..31

    float mean[L_][C_];
    int   vld[L_];
    float pc_local = 0.0f;

#pragma unroll
    for (int l = 0; l < L_; l++) {
        const int c = g_counts[b * L_ + l];
        vld[l] = (c > 1);
        const float inv = 1.0f / (float)max(c, 1);
#pragma unroll
        for (int ch = 0; ch < C_; ch++) {
            const float m = g_sums[(b * L_ + l) * C_ + ch] * inv;
            mean[l][ch] = m;
            g_means[(b * (L_ + 1) + (l + 1)) * C_ + ch] = m;
        }
        g_valid[b * (L_ + 1) + (l + 1)] = vld[l];
        if (vld[l]) pc_local += (float)c;
    }
#pragma unroll
    for (int ch = 0; ch < C_; ch++) g_means[b * (L_ + 1) * C_ + ch] = 0.0f;
    g_valid[b * (L_ + 1)] = 0;

    // push loss over lane pairs (i < j, both valid)
    float psum = 0.0f;
    int npairs = 0;
#pragma unroll
    for (int i = 0; i < L_; i++) {
#pragma unroll
        for (int j = i + 1; j < L_; j++) {
            if (vld[i] && vld[j]) {
                float sq = 0.0f;
#pragma unroll
                for (int ch = 0; ch < C_; ch++) {
                    const float d = mean[i][ch] - mean[j][ch];
                    sq = fmaf(d, d, sq);
                }
                const float pd = sqrtf(fmaxf(sq, 1e-12f));
                const float ph = fmaxf(DELTA_D - pd, 0.0f);
                psum += ph * ph;
                npairs++;
            }
        }
    }
    const float var_b = (npairs > 0) ? psum / (float)npairs : 0.0f;
    const float has   = (npairs > 0) ? 1.0f : 0.0f;

    float var_sum = var_b, nb = has, pc = pc_local;
#pragma unroll
    for (int off = 16; off > 0; off >>= 1) {
        var_sum += __shfl_down_sync(0xffffffffu, var_sum, off);
        nb      += __shfl_down_sync(0xffffffffu, nb, off);
        pc      += __shfl_down_sync(0xffffffffu, pc, off);
    }
    if (threadIdx.x == 0) {
        g_scalars[1] = pc;
        g_scalars[2] = (nb > 0.0f) ? var_sum / fmaxf(nb, 1.0f) : 0.0f;
    }
}

// --------------------------------------------------------------------------
// Pass 2: per-point pull hinge^2 from packed uint8 labels (4 B/group instead
// of 16 B). Means cached in shared; one global atomic per block.
__global__ void dist_kernel(const float* __restrict__ emb) {
    const int b = blockIdx.y;
    __shared__ float sm[(L_ + 1) * C_];
    __shared__ int   sv[L_ + 1];
    if (threadIdx.x < (L_ + 1) * C_) sm[threadIdx.x] = g_means[b * (L_ + 1) * C_ + threadIdx.x];
    if (threadIdx.x < (L_ + 1))      sv[threadIdx.x] = g_valid[b * (L_ + 1) + threadIdx.x];
    __syncthreads();

    const unsigned* tp = g_tpack + (size_t)b * NVEC;
    const float4*   e4 = (const float4*)(emb + (size_t)b * C_ * P_);

    float local = 0.0f;
    for (int i = blockIdx.x * blockDim.x + threadIdx.x; i < NVEC;
         i += gridDim.x * blockDim.x) {
        const unsigned u = __ldcs(&tp[i]);
        float4 ev[C_];
#pragma unroll
        for (int c = 0; c < C_; c++) ev[c] = __ldcs(&e4[(size_t)c * NVEC + i]);

        int tj[4] = {(int)(u & 255u), (int)((u >> 8) & 255u),
                     (int)((u >> 16) & 255u), (int)(u >> 24)};
#pragma unroll
        for (int j = 0; j < 4; j++) {
            const int tt = tj[j];
            if (sv[tt]) {
                float sq = 0.0f;
#pragma unroll
                for (int c = 0; c < C_; c++) {
                    const float d = ((const float*)&ev[c])[j] - sm[tt * C_ + c];
                    sq = fmaf(d, d, sq);
                }
                const float dist = sqrt_approx(fmaxf(sq, 1e-12f));
                const float h = dist - DELTA_V;
                if (h > 0.0f) local = fmaf(h, h, local);
            }
        }
    }

    // warp reduce
#pragma unroll
    for (int off = 16; off > 0; off >>= 1)
        local += __shfl_down_sync(0xffffffffu, local, off);

    __shared__ float sred;
    if (threadIdx.x == 0) sred = 0.0f;
    __syncthreads();
    if ((threadIdx.x & 31) == 0) atomicAdd(&sred, local);
    __syncthreads();
    if (threadIdx.x == 0) atomicAdd(&g_scalars[0], sred);
}

// --------------------------------------------------------------------------
__global__ void finalize_kernel(float* __restrict__ out) {
    const float ds = g_scalars[0];
    const float pc = g_scalars[1];
    const float dist_loss = (pc > 0.0f) ? ds / fmaxf(pc, 1.0f) : 0.0f;
    out[0] = dist_loss + g_scalars[2];
}

// --------------------------------------------------------------------------
extern "C" void kernel_launch(void* const* d_in, const int* in_sizes, int n_in,
                              void* d_out, int out_size) {
    const int*   tg  = (const int*)d_in[0];    // targets [32,360,640] int32
    const float* emb = (const float*)d_in[1];  // embedding [32,4,360,640] f32
    float* out = (float*)d_out;

    dim3 grid(NBLK, B_);
    zero_kernel<<<1, 1024>>>();
    accum_kernel<<<grid, TPB>>>(tg, emb);
    means_kernel<<<1, 32>>>();
    dist_kernel<<<grid, TPB>>>(emb);
    finalize_kernel<<<1, 1>>>(out);
}

// round 11
// speedup vs baseline: 1.2215x; 1.0225x over previous
#include <cuda_runtime.h>
#include <cuda_bf16.h>

// Problem constants (fixed shapes per reference setup_inputs)
#define B_   32
#define C_   4
#define P_   (360 * 640)      // 230400
#define L_   5
#define NVEC (P_ / 4)         // 57600 vec4 groups per batch

#define NBLK 60               // blocks per batch (champion config)
#define TPB  256

#define DELTA_V 1.0f
#define DELTA_D 6.0f

// ---- static scratch (no device allocation allowed; zero-initialized at load) ----
__device__ float    g_sums[B_ * L_ * C_];        // [B][L][C]   (reset by means each replay)
__device__ int      g_counts[B_ * L_];           // [B][L]      (reset by means each replay)
__device__ float    g_means[B_ * (L_ + 1) * C_]; // [B][6][4], lane 0 = zeros
__device__ int      g_valid[B_ * (L_ + 1)];      // [B][6], lane 0 = 0
__device__ float    g_scalars[4];                // 0: dist_sum, 1: point_count, 2: var_loss
__device__ int      g_dist_done;                 // dist last-block counter (self-resetting)
__device__ unsigned g_tpack[B_ * NVEC];          // 4 uint8 labels per word

__device__ __forceinline__ float sqrt_approx(float x) {
    float r;
    asm("sqrt.approx.f32 %0, %1;" : "=f"(r) : "f"(x));
    return r;
}

// --------------------------------------------------------------------------
// Pass 1: per-(batch, lane) segment counts and channel sums (branch-free
// select + FFMA, plain C so ptxas owns scheduling), plus uint8 label re-pack
// for pass 2. Streaming loads (no reuse).  [R10 verbatim]
__global__ void accum_kernel(const int* __restrict__ tg,
                             const float* __restrict__ emb) {
    const int b = blockIdx.y;
    const int4*   t4 = (const int4*)(tg + (size_t)b * P_);
    const float4* e4 = (const float4*)(emb + (size_t)b * C_ * P_);
    unsigned*     tp = g_tpack + (size_t)b * NVEC;

    float s[L_][C_];
    int cnt[L_];
#pragma unroll
    for (int l = 0; l < L_; l++) {
        cnt[l] = 0;
#pragma unroll
        for (int c = 0; c < C_; c++) s[l][c] = 0.0f;
    }

    for (int i = blockIdx.x * blockDim.x + threadIdx.x; i < NVEC;
         i += gridDim.x * blockDim.x) {
        int4 tv = __ldcs(&t4[i]);
        float4 ev[C_];
#pragma unroll
        for (int c = 0; c < C_; c++) ev[c] = __ldcs(&e4[(size_t)c * NVEC + i]);

        tp[i] = (unsigned)tv.x | ((unsigned)tv.y << 8) |
                ((unsigned)tv.z << 16) | ((unsigned)tv.w << 24);

        int tj[4] = {tv.x, tv.y, tv.z, tv.w};
#pragma unroll
        for (int j = 0; j < 4; j++) {
            const int tt = tj[j];
#pragma unroll
            for (int l = 0; l < L_; l++) {
                const bool m = (tt == l + 1);
                cnt[l] += m ? 1 : 0;
                const float fm = m ? 1.0f : 0.0f;
#pragma unroll
                for (int c = 0; c < C_; c++)
                    s[l][c] = fmaf(fm, ((const float*)&ev[c])[j], s[l][c]);
            }
        }
    }

    // warp reduce
#pragma unroll
    for (int l = 0; l < L_; l++) {
#pragma unroll
        for (int off = 16; off > 0; off >>= 1) {
            cnt[l] += __shfl_down_sync(0xffffffffu, cnt[l], off);
#pragma unroll
            for (int c = 0; c < C_; c++)
                s[l][c] += __shfl_down_sync(0xffffffffu, s[l][c], off);
        }
    }

    __shared__ float ss[L_ * C_];
    __shared__ int   sc[L_];
    if (threadIdx.x < L_ * C_) ss[threadIdx.x] = 0.0f;
    if (threadIdx.x < L_)      sc[threadIdx.x] = 0;
    __syncthreads();

    if ((threadIdx.x & 31) == 0) {
#pragma unroll
        for (int l = 0; l < L_; l++) {
            atomicAdd(&sc[l], cnt[l]);
#pragma unroll
            for (int c = 0; c < C_; c++) atomicAdd(&ss[l * C_ + c], s[l][c]);
        }
    }
    __syncthreads();

    if (threadIdx.x < L_ * C_)
        atomicAdd(&g_sums[b * L_ * C_ + threadIdx.x], ss[threadIdx.x]);
    if (threadIdx.x < L_)
        atomicAdd(&g_counts[b * L_ + threadIdx.x], sc[threadIdx.x]);
}

// --------------------------------------------------------------------------
// Means, validity, point_count, push loss; also RESETS g_sums/g_counts and
// g_scalars[0] for the next graph replay (replaces zero_kernel).
// 1 warp, thread b handles batch b.
__global__ void means_kernel() {
    const int b = threadIdx.x;  // 0..31

    float mean[L_][C_];
    int   vld[L_];
    float pc_local = 0.0f;

#pragma unroll
    for (int l = 0; l < L_; l++) {
        const int c = g_counts[b * L_ + l];
        vld[l] = (c > 1);
        const float inv = 1.0f / (float)max(c, 1);
#pragma unroll
        for (int ch = 0; ch < C_; ch++) {
            const float m = g_sums[(b * L_ + l) * C_ + ch] * inv;
            mean[l][ch] = m;
            g_means[(b * (L_ + 1) + (l + 1)) * C_ + ch] = m;
            g_sums[(b * L_ + l) * C_ + ch] = 0.0f;   // reset for next replay
        }
        g_valid[b * (L_ + 1) + (l + 1)] = vld[l];
        g_counts[b * L_ + l] = 0;                    // reset for next replay
        if (vld[l]) pc_local += (float)c;
    }
#pragma unroll
    for (int ch = 0; ch < C_; ch++) g_means[b * (L_ + 1) * C_ + ch] = 0.0f;
    g_valid[b * (L_ + 1)] = 0;

    // push loss over lane pairs (i < j, both valid)
    float psum = 0.0f;
    int npairs = 0;
#pragma unroll
    for (int i = 0; i < L_; i++) {
#pragma unroll
        for (int j = i + 1; j < L_; j++) {
            if (vld[i] && vld[j]) {
                float sq = 0.0f;
#pragma unroll
                for (int ch = 0; ch < C_; ch++) {
                    const float d = mean[i][ch] - mean[j][ch];
                    sq = fmaf(d, d, sq);
                }
                const float pd = sqrtf(fmaxf(sq, 1e-12f));
                const float ph = fmaxf(DELTA_D - pd, 0.0f);
                psum += ph * ph;
                npairs++;
            }
        }
    }
    const float var_b = (npairs > 0) ? psum / (float)npairs : 0.0f;
    const float has   = (npairs > 0) ? 1.0f : 0.0f;

    float var_sum = var_b, nb = has, pc = pc_local;
#pragma unroll
    for (int off = 16; off > 0; off >>= 1) {
        var_sum += __shfl_down_sync(0xffffffffu, var_sum, off);
        nb      += __shfl_down_sync(0xffffffffu, nb, off);
        pc      += __shfl_down_sync(0xffffffffu, pc, off);
    }
    if (threadIdx.x == 0) {
        g_scalars[0] = 0.0f;   // dist accumulator (reset before dist runs)
        g_scalars[1] = pc;
        g_scalars[2] = (nb > 0.0f) ? var_sum / fmaxf(nb, 1.0f) : 0.0f;
        __threadfence();
    }
}

// --------------------------------------------------------------------------
// Pass 2: per-point pull hinge^2 from packed uint8 labels (4 B/group).
// Means cached in shared; one global atomic per block; last-finishing block
// writes the final scalar (replaces finalize_kernel).
__global__ void dist_kernel(const float* __restrict__ emb,
                            float* __restrict__ out) {
    const int b = blockIdx.y;
    __shared__ float sm[(L_ + 1) * C_];
    __shared__ int   sv[L_ + 1];
    if (threadIdx.x < (L_ + 1) * C_) sm[threadIdx.x] = g_means[b * (L_ + 1) * C_ + threadIdx.x];
    if (threadIdx.x < (L_ + 1))      sv[threadIdx.x] = g_valid[b * (L_ + 1) + threadIdx.x];
    __syncthreads();

    const unsigned* tp = g_tpack + (size_t)b * NVEC;
    const float4*   e4 = (const float4*)(emb + (size_t)b * C_ * P_);

    float local = 0.0f;
    for (int i = blockIdx.x * blockDim.x + threadIdx.x; i < NVEC;
         i += gridDim.x * blockDim.x) {
        const unsigned u = __ldcs(&tp[i]);
        float4 ev[C_];
#pragma unroll
        for (int c = 0; c < C_; c++) ev[c] = __ldcs(&e4[(size_t)c * NVEC + i]);

        int tj[4] = {(int)(u & 255u), (int)((u >> 8) & 255u),
                     (int)((u >> 16) & 255u), (int)(u >> 24)};
#pragma unroll
        for (int j = 0; j < 4; j++) {
            const int tt = tj[j];
            if (sv[tt]) {
                float sq = 0.0f;
#pragma unroll
                for (int c = 0; c < C_; c++) {
                    const float d = ((const float*)&ev[c])[j] - sm[tt * C_ + c];
                    sq = fmaf(d, d, sq);
                }
                const float dist = sqrt_approx(fmaxf(sq, 1e-12f));
                const float h = dist - DELTA_V;
                if (h > 0.0f) local = fmaf(h, h, local);
            }
        }
    }

    // warp reduce
#pragma unroll
    for (int off = 16; off > 0; off >>= 1)
        local += __shfl_down_sync(0xffffffffu, local, off);

    __shared__ float sred;
    if (threadIdx.x == 0) sred = 0.0f;
    __syncthreads();
    if ((threadIdx.x & 31) == 0) atomicAdd(&sred, local);
    __syncthreads();

    if (threadIdx.x == 0) {
        atomicAdd(&g_scalars[0], sred);
        __threadfence();
        const int old = atomicAdd(&g_dist_done, 1);
        if (old == NBLK * B_ - 1) {
            const float ds = g_scalars[0];
            const float pc = g_scalars[1];
            const float dl = (pc > 0.0f) ? ds / fmaxf(pc, 1.0f) : 0.0f;
            out[0] = dl + g_scalars[2];
            g_dist_done = 0;       // reset for next graph replay
            __threadfence();
        }
    }
}

// --------------------------------------------------------------------------
extern "C" void kernel_launch(void* const* d_in, const int* in_sizes, int n_in,
                              void* d_out, int out_size) {
    const int*   tg  = (const int*)d_in[0];    // targets [32,360,640] int32
    const float* emb = (const float*)d_in[1];  // embedding [32,4,360,640] f32
    float* out = (float*)d_out;

    dim3 grid(NBLK, B_);
    accum_kernel<<<grid, TPB>>>(tg, emb);
    means_kernel<<<1, 32>>>();
    dist_kernel<<<grid, TPB>>>(emb, out);
}